// round 3
// baseline (speedup 1.0000x reference)
#include <cuda_runtime.h>
#include <math.h>

// ---------------------------------------------------------------------------
// Fixed problem shapes (fast path: uniform peaks)
// ---------------------------------------------------------------------------
#define BATCH      2
#define NUM_PEAKS  64
#define PEAKS      128          // BATCH * NUM_PEAKS
#define PSIZE      1000
#define MOTIF      640
#define HID        256
#define DEPTH      7
#define PROF_K     75
#define MAXLEN     1008         // padded row stride (floats)
#define GL_TOTAL   128000       // BATCH * NUM_PEAKS * PSIZE

// Ping-pong activation buffers: [2][peak][channel][MAXLEN]
__device__ float g_buf[2][PEAKS * HID * MAXLEN];
// Per-(peak, channel) mean of the final feature map
__device__ float g_mean[PEAKS * HID];

__device__ __forceinline__ float softplus_f(float x) {
    return (x > 20.f) ? x : log1pf(expf(x));
}

// ---------------------------------------------------------------------------
// Kernel 1: 1x1 motif projection  h[n][c][l] = sum_m x[gl][m] * w[c][m] + b[c]
// Tiling: 128 gl x 128 c per block, 256 threads, 8x8 per thread (stride 16).
// ---------------------------------------------------------------------------
__global__ __launch_bounds__(256)
void proj_kernel(const float* __restrict__ x,
                 const float* __restrict__ w,
                 const float* __restrict__ bias) {
    __shared__ float Ws[8][128];   // [m][c]
    __shared__ float Xs[8][128];   // [m][gl]

    const int tid = threadIdx.x;
    const int tx  = tid & 15;       // gl lane
    const int ty  = tid >> 4;       // c lane
    const int gl0 = blockIdx.x * 128;
    const int c0  = blockIdx.y * 128;

    float acc[8][8];
#pragma unroll
    for (int i = 0; i < 8; i++)
#pragma unroll
        for (int j = 0; j < 8; j++) acc[i][j] = 0.f;

    // loader mapping: each thread brings one float4 per smem tile
    const int lc = tid >> 1;               // 0..127 (row: c or gl)
    const int lm = (tid & 1) * 4;          // m sub-offset 0 or 4

    for (int m0 = 0; m0 < MOTIF; m0 += 8) {
        // Ws: w[(c0+lc)*MOTIF + m0+lm .. +3]
        float4 wv4 = *(const float4*)&w[(c0 + lc) * MOTIF + m0 + lm];
        Ws[lm + 0][lc] = wv4.x;
        Ws[lm + 1][lc] = wv4.y;
        Ws[lm + 2][lc] = wv4.z;
        Ws[lm + 3][lc] = wv4.w;
        // Xs: x[(gl0+lc)*MOTIF + m0+lm .. +3]
        float4 xv4 = *(const float4*)&x[(size_t)(gl0 + lc) * MOTIF + m0 + lm];
        Xs[lm + 0][lc] = xv4.x;
        Xs[lm + 1][lc] = xv4.y;
        Xs[lm + 2][lc] = xv4.z;
        Xs[lm + 3][lc] = xv4.w;
        __syncthreads();

        for (int mm = 0; mm < 8; mm++) {
            float wv[8], xv[8];
#pragma unroll
            for (int i = 0; i < 8; i++) wv[i] = Ws[mm][ty + i * 16];
#pragma unroll
            for (int j = 0; j < 8; j++) xv[j] = Xs[mm][tx + j * 16];
#pragma unroll
            for (int i = 0; i < 8; i++)
#pragma unroll
                for (int j = 0; j < 8; j++)
                    acc[i][j] = fmaf(wv[i], xv[j], acc[i][j]);
        }
        __syncthreads();
    }

#pragma unroll
    for (int i = 0; i < 8; i++) {
        const int c = c0 + ty + i * 16;
        const float bv = bias[c];
#pragma unroll
        for (int j = 0; j < 8; j++) {
            const int gl = gl0 + tx + j * 16;
            const int n  = gl / PSIZE;
            const int l  = gl - n * PSIZE;
            g_buf[0][((size_t)n * HID + c) * MAXLEN + l] = acc[i][j] + bv;
        }
    }
}

// ---------------------------------------------------------------------------
// Kernel 2: dilated conv layer (K=3) + bias + ReLU + residual (middle tap)
// out[n][co][l] = relu(sum_{ci,k} in[n][ci][l+k*d] * w[co][ci][k] + b[co])
//                 + in[n][co][l+d]
// Block: 128 co x 128 l for one peak; CI chunks of 8.
// ---------------------------------------------------------------------------
__global__ __launch_bounds__(256)
void conv_kernel(int src,
                 const float* __restrict__ w,     // [co][ci][3] for this layer
                 const float* __restrict__ bias,  // [co]
                 int len_in, int len_out, int dil) {
    __shared__ float Ws[3][8][128];   // [k][ci][co]
    __shared__ float Xs[3][8][128];   // [k][ci][l]

    const float* __restrict__ in  = g_buf[src];
    float* __restrict__       out = g_buf[src ^ 1];

    const int tid = threadIdx.x;
    const int tx  = tid & 15;        // l lane
    const int ty  = tid >> 4;        // co lane
    const int l0  = blockIdx.x * 128;
    const int co0 = blockIdx.y * 128;
    const int n   = blockIdx.z;

    float acc[8][8];
#pragma unroll
    for (int i = 0; i < 8; i++)
#pragma unroll
        for (int j = 0; j < 8; j++) acc[i][j] = 0.f;

    // weight loader: thread -> (co = tid/2, 12 consecutive (ci,k) entries)
    const int wco  = tid >> 1;
    const int woff = (tid & 1) * 12;

    for (int ci0 = 0; ci0 < HID; ci0 += 8) {
        // --- load weights: w[(co0+wco)*768 + ci0*3 + woff .. +11]
        {
            const float* wp = &w[(size_t)(co0 + wco) * (HID * 3) + ci0 * 3 + woff];
            float4 a = *(const float4*)(wp + 0);
            float4 b = *(const float4*)(wp + 4);
            float4 c = *(const float4*)(wp + 8);
            float tmp[12] = {a.x, a.y, a.z, a.w, b.x, b.y, b.z, b.w, c.x, c.y, c.z, c.w};
#pragma unroll
            for (int r = 0; r < 12; r++) {
                int q  = woff + r;
                int ci = q / 3;
                int k  = q - ci * 3;
                Ws[k][ci][wco] = tmp[r];
            }
        }
        // --- load inputs: Xs[k][ci][l] = in[n][ci0+ci][l0+l+k*d]  (guarded)
        for (int idx = tid; idx < 3 * 8 * 128; idx += 256) {
            int l    = idx & 127;
            int pair = idx >> 7;          // 0..23
            int ci   = pair / 3;
            int k    = pair - ci * 3;
            int g    = l0 + l + k * dil;
            Xs[k][ci][l] = (g < len_in)
                ? in[((size_t)n * HID + ci0 + ci) * MAXLEN + g] : 0.f;
        }
        __syncthreads();

        for (int ci = 0; ci < 8; ci++) {
#pragma unroll
            for (int k = 0; k < 3; k++) {
                float wv[8], xv[8];
#pragma unroll
                for (int i = 0; i < 8; i++) wv[i] = Ws[k][ci][ty + i * 16];
#pragma unroll
                for (int j = 0; j < 8; j++) xv[j] = Xs[k][ci][tx + j * 16];
#pragma unroll
                for (int i = 0; i < 8; i++)
#pragma unroll
                    for (int j = 0; j < 8; j++)
                        acc[i][j] = fmaf(wv[i], xv[j], acc[i][j]);
            }
        }
        __syncthreads();
    }

    // epilogue: bias + relu + residual
#pragma unroll
    for (int i = 0; i < 8; i++) {
        const int co = co0 + ty + i * 16;
        const float bv = bias[co];
#pragma unroll
        for (int j = 0; j < 8; j++) {
            const int l = l0 + tx + j * 16;
            if (l < len_out) {
                float v = fmaxf(acc[i][j] + bv, 0.f)
                        + in[((size_t)n * HID + co) * MAXLEN + l + dil];
                out[((size_t)n * HID + co) * MAXLEN + l] = v;
            }
        }
    }
}

// ---------------------------------------------------------------------------
// Kernel 3: per-(peak, channel) mean over length
// ---------------------------------------------------------------------------
__global__ __launch_bounds__(256)
void mean_kernel(int src, int len) {
    const float* __restrict__ in = g_buf[src];
    const int row  = blockIdx.x * 8 + (threadIdx.x >> 5);   // 32768 rows
    const int lane = threadIdx.x & 31;
    const float* p = in + (size_t)row * MAXLEN;
    float s = 0.f;
    for (int l = lane; l < len; l += 32) s += p[l];
#pragma unroll
    for (int o = 16; o; o >>= 1) s += __shfl_xor_sync(0xFFFFFFFFu, s, o);
    if (lane == 0) g_mean[row] = s / (float)len;
}

// ---------------------------------------------------------------------------
// Kernel 4: atpm head  out[n] = softplus(dot(mean[n], w_atpm) + b_atpm)
// ---------------------------------------------------------------------------
__global__ __launch_bounds__(256)
void atpm_kernel(const float* __restrict__ w, const float* __restrict__ b,
                 float* __restrict__ out) {
    __shared__ float sh[256];
    const int n = blockIdx.x;
    const int t = threadIdx.x;
    sh[t] = g_mean[n * HID + t] * w[t];
    __syncthreads();
    for (int s = 128; s > 0; s >>= 1) {
        if (t < s) sh[t] += sh[t + s];
        __syncthreads();
    }
    if (t == 0) out[n] = softplus_f(sh[0] + b[0]);
}

// ---------------------------------------------------------------------------
// Kernel 5: profile conv (K=75, 256 -> 1) + softplus
// One block per peak; loop channels, stage row + weight row in smem.
// ---------------------------------------------------------------------------
__global__ __launch_bounds__(256)
void prof_kernel(int src, const float* __restrict__ wp,
                 const float* __restrict__ bp, float* __restrict__ out,
                 int len_in, int len_out) {
    __shared__ float hrow[512];
    __shared__ float wrow[80];
    const float* __restrict__ in = g_buf[src];
    const int n = blockIdx.x;
    const int t = threadIdx.x;
    const int l0 = t;            // output 0..255
    const int l1 = t + 256;      // output 256..417 (guarded)

    float acc0 = 0.f, acc1 = 0.f;
    for (int c = 0; c < HID; c++) {
        for (int l = t; l < len_in; l += 256)
            hrow[l] = in[((size_t)n * HID + c) * MAXLEN + l];
        if (t < PROF_K) wrow[t] = wp[c * PROF_K + t];
        __syncthreads();

#pragma unroll 5
        for (int k = 0; k < PROF_K; k++)
            acc0 = fmaf(hrow[l0 + k], wrow[k], acc0);
        if (l1 < len_out) {
#pragma unroll 5
            for (int k = 0; k < PROF_K; k++)
                acc1 = fmaf(hrow[l1 + k], wrow[k], acc1);
        }
        __syncthreads();
    }
    const float bv = bp[0];
    out[PEAKS + (size_t)n * len_out + l0] = softplus_f(acc0 + bv);
    if (l1 < len_out)
        out[PEAKS + (size_t)n * len_out + l1] = softplus_f(acc1 + bv);
}

// ---------------------------------------------------------------------------
// Launch
// ---------------------------------------------------------------------------
extern "C" void kernel_launch(void* const* d_in, const int* in_sizes, int n_in,
                              void* d_out, int out_size) {
    const float* x = (const float*)d_in[0];

    // locate w_proj by its unique element count (robust to whether
    // max_n_peaks is materialized as a device input)
    int iw = -1;
    for (int i = 1; i < n_in; i++)
        if (in_sizes[i] == MOTIF * HID) { iw = i; break; }

    const float* w_proj = (const float*)d_in[iw + 0];
    const float* b_proj = (const float*)d_in[iw + 1];
    const float* w_dil  = (const float*)d_in[iw + 2];
    const float* b_dil  = (const float*)d_in[iw + 3];
    const float* w_prof = (const float*)d_in[iw + 4];
    const float* b_prof = (const float*)d_in[iw + 5];
    const float* w_atpm = (const float*)d_in[iw + 6];
    const float* b_atpm = (const float*)d_in[iw + 7];
    float* out = (float*)d_out;

    // 1) projection -> g_buf[0]
    proj_kernel<<<dim3(GL_TOTAL / 128, HID / 128), 256>>>(x, w_proj, b_proj);

    // 2) dilated conv tower (ping-pong)
    int len = PSIZE, src = 0;
    for (int i = 0; i < DEPTH; i++) {
        const int d  = 1 << (i + 1);
        const int lo = len - 2 * d;
        conv_kernel<<<dim3((lo + 127) / 128, HID / 128, PEAKS), 256>>>(
            src, w_dil + (size_t)i * HID * HID * 3, b_dil + i * HID, len, lo, d);
        src ^= 1;
        len = lo;
    }

    // 3) mean over length (final map: len == 492, src buffer)
    mean_kernel<<<(PEAKS * HID) / 8, 256>>>(src, len);

    // 4) atpm head -> out[0..127]
    atpm_kernel<<<PEAKS, 256>>>(w_atpm, b_atpm, out);

    // 5) profile conv -> out[128 .. 128 + 128*418)
    prof_kernel<<<PEAKS, 256>>>(src, w_prof, b_prof, out, len, len - PROF_K + 1);
}